// round 5
// baseline (speedup 1.0000x reference)
#include <cuda_runtime.h>
#include <math.h>

#define BN 8192
#define FN 8192
#define DN 1024
#define H1N 256
#define H2N 64
#define NZC 102
#define CAP 96
#define GWIDTH 0.11f

// ---------------- scratch (device globals; no allocations allowed) ----------
__device__ float g_a1[BN * H1N];     // pre-BN activations layer 1
__device__ float g_a2[BN * H2N];     // pre-BN activations layer 2
__device__ float g_sc1[H1N], g_sh1[H1N];
__device__ float g_sc2[H2N], g_sh2[H2N];
__device__ int   g_ind[BN];          // final argmax per row

// ---------------- threefry-2x32, key = (0, 42) ------------------------------
__device__ __forceinline__ void threefry2x32(unsigned int c0, unsigned int c1,
                                             unsigned int &o0, unsigned int &o1) {
    const unsigned int k0 = 0u, k1 = 42u;
    const unsigned int k2 = 0x1BD11BDAu ^ k0 ^ k1;
    unsigned int x0 = c0 + k0, x1 = c1 + k1;
#define TF_R(r) { x0 += x1; x1 = (x1 << (r)) | (x1 >> (32 - (r))); x1 ^= x0; }
    TF_R(13) TF_R(15) TF_R(26) TF_R(6)
    x0 += k1; x1 += k2 + 1u;
    TF_R(17) TF_R(29) TF_R(16) TF_R(24)
    x0 += k2; x1 += k0 + 2u;
    TF_R(13) TF_R(15) TF_R(26) TF_R(6)
    x0 += k0; x1 += k1 + 3u;
    TF_R(17) TF_R(29) TF_R(16) TF_R(24)
    x0 += k1; x1 += k2 + 4u;
    TF_R(13) TF_R(15) TF_R(26) TF_R(6)
    x0 += k2; x1 += k0 + 5u;
#undef TF_R
    o0 = x0; o1 = x1;
}

// jax partitionable 32-bit random bits:
//   counts1, counts2 = iota_2x32_shape(shape)   -> (0, j) for j < 2^32
//   bits1, bits2 = threefry2x32(key, counts)
//   bits = bits1 ^ bits2
__device__ __forceinline__ unsigned int jax_bits(unsigned int j) {
    unsigned int o0, o1;
    threefry2x32(0u, j, o0, o1);
    return o0 ^ o1;
}

// reference-matched gumbel: libdevice logf (same as XLA), no FMA contraction
__device__ __forceinline__ float gumbel_ref(unsigned int b) {
    float u = __uint_as_float((b >> 9) | 0x3F800000u) - 1.0f;   // [0,1)
    float U = __fmul_rn(0.001f, u);
    float t = __fadd_rn(U, 0.001f);          // [0.001, 0.002)
    float l1 = logf(t);
    float a  = __fadd_rn(-l1, 0.001f);       // (6.2156, 6.9088]
    return -logf(a);                          // [-1.93285, -1.82711]
}

// order-preserving float<->uint encoding (atomicMax on floats, any sign)
__device__ __forceinline__ unsigned int encf(float f) {
    unsigned int u = __float_as_uint(f);
    return (u & 0x80000000u) ? ~u : (u | 0x80000000u);
}
__device__ __forceinline__ float decf(unsigned int e) {
    unsigned int u = (e & 0x80000000u) ? (e ^ 0x80000000u) : ~e;
    return __uint_as_float(u);
}

// ---------------- K1: a1 = concat(x,y) @ W1 + b1 ----------------------------
__global__ __launch_bounds__(256) void k1_gemm1(const float* __restrict__ x,
                                                const float* __restrict__ y,
                                                const float* __restrict__ W1,
                                                const float* __restrict__ b1) {
    __shared__ float zs[8][NZC];
    const int rb = blockIdx.x * 8;
    const int tid = threadIdx.x;
    for (int i = tid; i < 8 * NZC; i += 256) {
        int r = i / NZC, c = i % NZC;
        zs[r][c] = (c < 100) ? x[(rb + r) * 100 + c] : y[(rb + r) * 2 + (c - 100)];
    }
    __syncthreads();
    const int col = tid;
    float acc[8];
#pragma unroll
    for (int r = 0; r < 8; r++) acc[r] = 0.0f;
    for (int k = 0; k < NZC; k++) {
        float w = W1[k * 256 + col];
#pragma unroll
        for (int r = 0; r < 8; r++) acc[r] = fmaf(zs[r][k], w, acc[r]);
    }
    const float bb = b1[col];
#pragma unroll
    for (int r = 0; r < 8; r++) g_a1[(rb + r) * 256 + col] = acc[r] + bb;
}

// ---------------- K2/K4: per-feature biased batch stats -> scale/shift ------
__global__ void kstats(int which, const float* __restrict__ gamma,
                       const float* __restrict__ beta) {
    const float* a = which ? g_a2 : g_a1;
    float* sc = which ? g_sc2 : g_sc1;
    float* sh = which ? g_sh2 : g_sh1;
    const int ncols = which ? H2N : H1N;
    const int col = blockIdx.x;
    const int tid = threadIdx.x;
    double s = 0.0, q = 0.0;
    for (int r = tid; r < BN; r += 256) {
        float v = a[r * ncols + col];
        s += (double)v;
        q += (double)v * (double)v;
    }
    __shared__ double ss[256], qq[256];
    ss[tid] = s; qq[tid] = q;
    __syncthreads();
    for (int st = 128; st > 0; st >>= 1) {
        if (tid < st) { ss[tid] += ss[tid + st]; qq[tid] += qq[tid + st]; }
        __syncthreads();
    }
    if (tid == 0) {
        double mean = ss[0] / (double)BN;
        double var  = qq[0] / (double)BN - mean * mean;
        float rstd = (float)(1.0 / sqrt(var + 1e-5));
        float scale = gamma[col] * rstd;
        sc[col] = scale;
        sh[col] = beta[col] - (float)mean * scale;
    }
}

// ---------------- K3: a2 = relu(BN(a1)) @ W2 + b2 ---------------------------
__global__ __launch_bounds__(256) void k3_gemm2(const float* __restrict__ W2,
                                                const float* __restrict__ b2) {
    __shared__ float h1s[16][256];
    const int rb = blockIdx.x * 16;
    const int tid = threadIdx.x;
#pragma unroll 4
    for (int r = 0; r < 16; r++) {
        float v = g_a1[(rb + r) * 256 + tid] * g_sc1[tid] + g_sh1[tid];
        h1s[r][tid] = fmaxf(v, 0.0f);
    }
    __syncthreads();
    const int c  = tid & 63;
    const int rq = tid >> 6;
    float acc[4] = {0.f, 0.f, 0.f, 0.f};
    for (int k = 0; k < 256; k++) {
        float w = W2[k * 64 + c];
#pragma unroll
        for (int i = 0; i < 4; i++) acc[i] = fmaf(h1s[rq * 4 + i][k], w, acc[i]);
    }
#pragma unroll
    for (int i = 0; i < 4; i++)
        g_a2[(rb + rq * 4 + i) * 64 + c] = acc[i] + b2[c];
}

// ---------------- K5: fused logits GEMM + bounded-gumbel candidate argmax ---
// Gumbel noise lies in [-1.93285, -1.82711] (width 0.1058), so only features
// with logit >= rowmax - 0.1058 can win. Bulk pass keeps a running per-row max
// (order-encoded smem atomicMax); candidates within GWIDTH of any partial max
// form a safe superset. Candidates get the exact threefry+logf evaluation in
// the reference's post-/TEMP domain.
__global__ __launch_bounds__(256) void k5_argmax(const float* __restrict__ W3,
                                                 const float* __restrict__ b3) {
    __shared__ float h2s[16][64];
    __shared__ unsigned int smaxe[16];
    __shared__ int scnt[16];
    __shared__ int cand[16][CAP];
    __shared__ float rv[256];
    __shared__ int   rf[256];
    const int tid = threadIdx.x;
    const int rb  = blockIdx.x * 16;

    for (int i = tid; i < 16 * 64; i += 256) {
        int lr = i >> 6, k = i & 63;
        float v = g_a2[(rb + lr) * 64 + k] * g_sc2[k] + g_sh2[k];
        h2s[lr][k] = fmaxf(v, 0.0f);
    }
    if (tid < 16) { smaxe[tid] = encf(-1e30f); scnt[tid] = 0; }
    __syncthreads();

    for (int f0 = 0; f0 < FN; f0 += 256) {
        const int f = f0 + tid;
        float acc[16];
#pragma unroll
        for (int r = 0; r < 16; r++) acc[r] = 0.0f;
#pragma unroll 4
        for (int k0 = 0; k0 < 64; k0 += 4) {
            float w0 = W3[(k0 + 0) * FN + f];
            float w1 = W3[(k0 + 1) * FN + f];
            float w2 = W3[(k0 + 2) * FN + f];
            float w3v = W3[(k0 + 3) * FN + f];
#pragma unroll
            for (int r = 0; r < 16; r++) {
                float4 h = *reinterpret_cast<const float4*>(&h2s[r][k0]);
                acc[r] = fmaf(h.x, w0, acc[r]);
                acc[r] = fmaf(h.y, w1, acc[r]);
                acc[r] = fmaf(h.z, w2, acc[r]);
                acc[r] = fmaf(h.w, w3v, acc[r]);
            }
        }
        const float bf = b3[f];
        // phase 1: push row maxima
#pragma unroll
        for (int r = 0; r < 16; r++) {
            acc[r] += bf;
            unsigned int e = *(volatile unsigned int*)&smaxe[r];
            if (acc[r] > decf(e)) atomicMax(&smaxe[r], encf(acc[r]));
        }
        __syncthreads();
        // phase 2: append candidates vs running max (any partial max <= final
        // max keeps this a superset of the true candidate set)
#pragma unroll
        for (int r = 0; r < 16; r++) {
            unsigned int e = *(volatile unsigned int*)&smaxe[r];
            if (acc[r] > decf(e) - GWIDTH) {
                int pos = atomicAdd(&scnt[r], 1);
                if (pos < CAP) cand[r][pos] = f;
            }
        }
    }
    __syncthreads();

    // exact refine per row, in the reference's (logits+g)/TEMP domain
    for (int r = 0; r < 16; r++) {
        const int row = rb + r;
        const int c = scnt[r];
        float bestv = -1e30f;
        int   bestf = 0x7FFFFFFF;
        if (c <= CAP) {
            if (tid < c) {
                const int f = cand[r][tid];
                float dot = 0.0f;
#pragma unroll
                for (int k = 0; k < 64; k++)
                    dot = fmaf(h2s[r][k], W3[k * FN + f], dot);
                float logit = __fadd_rn(dot, b3[f]);
                float g = gumbel_ref(jax_bits((unsigned)row * 8192u + (unsigned)f));
                bestv = __fdiv_rn(__fadd_rn(logit, g), 0.1f);
                bestf = f;
            }
        } else {
            // overflow fallback: exact scan of the whole row (rare)
            for (int f = tid; f < FN; f += 256) {
                float dot = 0.0f;
#pragma unroll
                for (int k = 0; k < 64; k++)
                    dot = fmaf(h2s[r][k], W3[k * FN + f], dot);
                float logit = __fadd_rn(dot, b3[f]);
                float g = gumbel_ref(jax_bits((unsigned)row * 8192u + (unsigned)f));
                float v = __fdiv_rn(__fadd_rn(logit, g), 0.1f);
                if (v > bestv || (v == bestv && f < bestf)) { bestv = v; bestf = f; }
            }
        }
        rv[tid] = bestv; rf[tid] = bestf;
        __syncthreads();
        for (int s = 128; s > 0; s >>= 1) {
            if (tid < s) {
                float bv = rv[tid + s]; int bfi = rf[tid + s];
                if (bv > rv[tid] || (bv == rv[tid] && bfi < rf[tid])) {
                    rv[tid] = bv; rf[tid] = bfi;
                }
            }
            __syncthreads();
        }
        if (tid == 0) g_ind[row] = rf[0];
        __syncthreads();
    }
}

// ---------------- K7: out[row] = codebook[ind[row]] -------------------------
__global__ void k7_gather(const float* __restrict__ codebook, float* __restrict__ out) {
    const int row = blockIdx.x;
    const int ind = g_ind[row];
    const float4* src = reinterpret_cast<const float4*>(codebook + (size_t)ind * DN);
    float4* dst = reinterpret_cast<float4*>(out + (size_t)row * DN);
    dst[threadIdx.x] = src[threadIdx.x];  // 256 threads * 16B = 4KB row
}

// ---------------- launch ----------------------------------------------------
extern "C" void kernel_launch(void* const* d_in, const int* in_sizes, int n_in,
                              void* d_out, int out_size) {
    const float* x   = (const float*)d_in[0];
    const float* y   = (const float*)d_in[1];
    const float* W1  = (const float*)d_in[2];
    const float* b1  = (const float*)d_in[3];
    const float* g1  = (const float*)d_in[4];
    const float* be1 = (const float*)d_in[5];
    const float* W2  = (const float*)d_in[6];
    const float* b2  = (const float*)d_in[7];
    const float* g2  = (const float*)d_in[8];
    const float* be2 = (const float*)d_in[9];
    const float* W3  = (const float*)d_in[10];
    const float* b3  = (const float*)d_in[11];
    const float* cb  = (const float*)d_in[12];
    float* out = (float*)d_out;

    k1_gemm1<<<BN / 8, 256>>>(x, y, W1, b1);
    kstats<<<H1N, 256>>>(0, g1, be1);
    k3_gemm2<<<BN / 16, 256>>>(W2, b2);
    kstats<<<H2N, 256>>>(1, g2, be2);
    k5_argmax<<<BN / 16, 256>>>(W3, b3);
    k7_gather<<<BN, 256>>>(cb, out);
}